// round 17
// baseline (speedup 1.0000x reference)
#include <cuda_runtime.h>
#include <cuda_bf16.h>
#include <cstdint>

#define WARPS   12
#define THREADS (WARPS * 32)
#define N_UNITS 16384     // 4096 tiles * 4 factors

// smem byte layout
#define S_W1   0                          // 16KB: W1 bf16 [k=128][n=64], swizzled
#define S_H    16384                      // 12 warps x 8KB: h fp32 [32][64], float4-slot swizzle
#define S_T    (S_H + WARPS*8192)         // 12 warps x 8KB: t fp32 [32][64], float4-slot swizzle
#define S_WGT  (S_T + WARPS*8192)         // 12 warps x 32 floats (16B aligned)
#define S_PAR  (S_WGT + WARPS*128)        // 129 floats: b1[64], W2[64], b2
#define SMEM_BYTES (S_PAR + 640)

static __device__ __forceinline__ uint32_t smem_u32(const void* p) {
    uint32_t a;
    asm("{ .reg .u64 t; cvta.to.shared.u64 t, %1; cvt.u32.u64 %0, t; }" : "=r"(a) : "l"(p));
    return a;
}
static __device__ __forceinline__ uint32_t pack2(float lo, float hi) {
    uint32_t r;
    asm("cvt.rn.bf16x2.f32 %0, %1, %2;" : "=r"(r) : "f"(hi), "f"(lo));
    return r;
}
static __device__ __forceinline__ void cp_async16(uint32_t dst, const void* src) {
    asm volatile("cp.async.cg.shared.global [%0], [%1], 16;" :: "r"(dst), "l"(src) : "memory");
}

#define LDS64F(f0,f1,addr) \
    asm volatile("ld.shared.v2.f32 {%0,%1}, [%2];" : "=f"(f0),"=f"(f1) : "r"(addr))
#define LDSM_X4T(b0,b1,b2,b3,addr) \
    asm volatile("ldmatrix.sync.aligned.m8n8.x4.trans.shared.b16 {%0,%1,%2,%3}, [%4];" \
        : "=r"(b0),"=r"(b1),"=r"(b2),"=r"(b3) : "r"(addr))
#define MMA16816(d,a0,a1,a2,a3,b0,b1) \
    asm volatile("mma.sync.aligned.m16n8k16.row.col.f32.bf16.bf16.f32 " \
        "{%0,%1,%2,%3}, {%4,%5,%6,%7}, {%8,%9}, {%0,%1,%2,%3};" \
        : "+f"((d)[0]),"+f"((d)[1]),"+f"((d)[2]),"+f"((d)[3]) \
        : "r"(a0),"r"(a1),"r"(a2),"r"(a3),"r"(b0),"r"(b1))

__global__ __launch_bounds__(THREADS, 1)
void kgat_sched_kernel(const float* __restrict__ node_emb,
                       const float* __restrict__ W1,
                       const float* __restrict__ b1,
                       const float* __restrict__ W2,
                       const float* __restrict__ b2,
                       const int*   __restrict__ users,
                       const int*   __restrict__ items,
                       const int*   __restrict__ utri,
                       const int*   __restrict__ itri,
                       float*       __restrict__ out)
{
    extern __shared__ char smem[];
    const int tid  = threadIdx.x;
    const int wid  = tid >> 5;
    const int lane = tid & 31;
    const int g    = lane >> 2;     // 0..7
    const int tc   = lane & 3;      // 0..3

    // ---- one-time: W1 -> bf16 smem [kk][n], slot swizzle s' = (n>>3)^(kk&7) ----
    for (int i = tid; i < 8192; i += THREADS) {
        int kk = i >> 6, n = i & 63;
        uint32_t byte = (uint32_t)kk * 128u + ((((uint32_t)n >> 3) ^ ((uint32_t)kk & 7)) << 4)
                        + (((uint32_t)n & 7) << 1);
        *(__nv_bfloat16*)(smem + S_W1 + byte) = __float2bfloat16(W1[i]);
    }
    float* sp = (float*)(smem + S_PAR);
    for (int i = tid; i < 129; i += THREADS)
        sp[i] = (i < 64) ? b1[i] : (i < 128 ? W2[i - 64] : b2[0]);
    __syncthreads();

    const uint32_t sb = smem_u32(smem);
    const uint32_t Wu = sb + S_W1;
    const uint32_t Hu = sb + S_H + (uint32_t)wid * 8192u;
    const uint32_t Tu = sb + S_T + (uint32_t)wid * 8192u;
    float*  stw   = (float*)(smem + S_T + wid * 8192);
    float*  swgt  = (float*)(smem + S_WGT) + wid * 32;
    float4* swgt4 = (float4*)swgt;
    const float* node_f = node_emb;
    const float b2v = sp[128];

    // ---- A-fragment address constants (per thread) ----
    const uint32_t x1   = (uint32_t)((lane >> 3) & 1) << 5;
    const uint32_t x2   = (uint32_t)((lane >> 4) & 1) << 6;
    const uint32_t y00  = x1 + x2;
    const uint32_t y01  = x1 + 64 - x2;
    const uint32_t y10  = 32 - x1 + x2;
    const uint32_t y11  = 96 - x1 - x2;
    const uint32_t aoff = (uint32_t)g * 256u
                        + (uint32_t)((((tc >> 1) ^ (g & 1)) & 1) << 4)
                        + (uint32_t)((tc & 1) << 3);
    const uint32_t BH = Hu + aoff;
    const uint32_t BT = Tu + aoff;

    const int stride = gridDim.x * WARPS;
    const int u0 = blockIdx.x * WARPS + wid;

    auto load_idx = [&](int u, int& hi, int& ti) {
        const int tile  = u >> 2;
        const int tower = tile >> 11;
        const int b     = (tile >> 1) & 1023;
        const int layer = tile & 1;
        const int* tri  = tower ? itri : utri;
        hi = tri[((b * 3 + 0) * 2 + layer) * 32 + lane];
        ti = tri[((b * 3 + 2) * 2 + layer) * 32 + lane];
    };
    auto issue_g = [&](int u, int idx, uint32_t buf) {
        const int f = u & 3;
        #pragma unroll
        for (int i = 0; i < 16; ++i) {
            const int r = 2 * i + (lane >> 4);
            const int c = lane & 15;
            const int nid = __shfl_sync(0xffffffffu, idx, r);
            cp_async16(buf + (uint32_t)((r * 16 + (c ^ (r & 15))) << 4),
                       node_f + (((size_t)nid * 4 + f) << 6) + (c << 2));
        }
        asm volatile("cp.async.commit_group;" ::: "memory");
    };

    // B fragment registers, rotated through the whole unit (gather-independent)
    uint32_t B0[8], B1[8];
    auto load_B = [&](int krow0) {
        const int krow = krow0 + (lane & 15);
        const int nsel = lane >> 4;
        #pragma unroll
        for (int np = 0; np < 4; ++np) {
            const int ntx = np * 2 + nsel;
            const uint32_t baddr = Wu + (uint32_t)krow * 128u
                                   + ((((uint32_t)ntx) ^ ((uint32_t)krow & 7)) << 4);
            LDSM_X4T(B0[np * 2], B1[np * 2], B0[np * 2 + 1], B1[np * 2 + 1], baddr);
        }
    };
    // 4 k-steps from staging at bufb; B for first ks preloaded; loads B for
    // knext after the last ks's MMAs (knext < 0: none)
    auto gemm_half = [&](float (*acc)[8][4], uint32_t bufb, int kbase, int knext) {
        #pragma unroll
        for (int ks = 0; ks < 4; ++ks) {
            const uint32_t c3_0 = (uint32_t)(((ks >> 1) & 1)    ) << 7;
            const uint32_t c3_1 = (uint32_t)(((ks >> 1) & 1) ^ 1) << 7;
            const uint32_t ya   = (ks & 1) ? y01 : y00;
            const uint32_t yb   = (ks & 1) ? y11 : y10;
            #pragma unroll
            for (int mt = 0; mt < 2; ++mt) {
                const uint32_t mb = bufb + (uint32_t)mt * 4096u;
                float f0, f1;
                uint32_t a0, a1r, a2r, a3r;
                LDS64F(f0, f1, mb + ya + c3_0);              a0  = pack2(f0, f1);
                LDS64F(f0, f1, mb + 2048u + ya + c3_1);      a1r = pack2(f0, f1);
                LDS64F(f0, f1, mb + yb + c3_0);              a2r = pack2(f0, f1);
                LDS64F(f0, f1, mb + 2048u + yb + c3_1);      a3r = pack2(f0, f1);
                #pragma unroll
                for (int nt = 0; nt < 8; ++nt)
                    MMA16816(acc[mt][nt], a0, a1r, a2r, a3r, B0[nt], B1[nt]);
            }
            if (ks < 3)          load_B(kbase + (ks + 1) * 16);
            else if (knext >= 0) load_B(knext);
        }
    };

    // ---- prologue: gather unit u0 (h group, then t group) ----
    if (u0 < N_UNITS) {
        int hi, ti;
        load_idx(u0, hi, ti);
        issue_g(u0, hi, Hu);
        issue_g(u0, ti, Tu);
    }

    for (int u = u0; u < N_UNITS; u += stride) {
        const int un = u + stride;
        const bool has_next = (un < N_UNITS);
        int hidx_n = 0, tidx_n = 0;
        if (has_next) load_idx(un, hidx_n, tidx_n);

        const int tile  = u >> 2;
        const int f     = u & 3;
        const int tower = tile >> 11;
        const int b     = (tile >> 1) & 1023;
        const int layer = tile & 1;

        // ---- origin slice (exact copy), overlaps in-flight gathers ----
        if (layer == 0) {
            const int oidx = (tower ? items : users)[b];
            float* outp = out + ((size_t)(tower * 3) * 1024 + b) * 256 + f * 64;
            ((float2*)outp)[lane] =
                ((const float2*)(node_emb + ((size_t)oidx * 4 + f) * 64))[lane];
        }

        float acc[2][8][4];
        #pragma unroll
        for (int mt = 0; mt < 2; ++mt)
            #pragma unroll
            for (int nt = 0; nt < 8; ++nt)
                #pragma unroll
                for (int e = 0; e < 4; ++e) acc[mt][nt][e] = 0.f;

        // B(k=0) loads overlap the h-wait (W1 is gather-independent)
        load_B(0);

        // ---- wait for h (FIFO: h oldest; t may stay in flight) ----
        asm volatile("cp.async.wait_group 1;" ::: "memory");
        __syncwarp();

        // ---- GEMM first half: k 0..63 from H; tail-loads B(k=64) pre-t-wait ----
        gemm_half(acc, BH, 0, 64);

        // ---- wait for t; ALL groups drain -> H LDS provably complete ----
        asm volatile("cp.async.wait_group 0;" ::: "memory");
        __syncwarp();

        // H buffer safely dead: refill for next unit (overlaps T-half + epilogue)
        if (has_next) issue_g(un, hidx_n, Hu);

        // ---- GEMM second half: k 64..127 from T ----
        gemm_half(acc, BT, 64, -1);

        // ---- logits: relu(C + b1) . W2 + b2 (b1/W2 via smem broadcast) ----
        float p[4] = {0.f, 0.f, 0.f, 0.f};
        #pragma unroll
        for (int nt = 0; nt < 8; ++nt) {
            const int n0 = nt * 8 + tc * 2;
            const float b1a = sp[n0], b1b = sp[n0 + 1];
            const float w2a = sp[64 + n0], w2b = sp[64 + n0 + 1];
            p[0] += fmaxf(acc[0][nt][0] + b1a, 0.f) * w2a + fmaxf(acc[0][nt][1] + b1b, 0.f) * w2b;
            p[1] += fmaxf(acc[0][nt][2] + b1a, 0.f) * w2a + fmaxf(acc[0][nt][3] + b1b, 0.f) * w2b;
            p[2] += fmaxf(acc[1][nt][0] + b1a, 0.f) * w2a + fmaxf(acc[1][nt][1] + b1b, 0.f) * w2b;
            p[3] += fmaxf(acc[1][nt][2] + b1a, 0.f) * w2a + fmaxf(acc[1][nt][3] + b1b, 0.f) * w2b;
        }
        float lg[4];
        #pragma unroll
        for (int e = 0; e < 4; ++e) {
            float v = p[e];
            v += __shfl_xor_sync(0xffffffffu, v, 1);
            v += __shfl_xor_sync(0xffffffffu, v, 2);
            lg[e] = v + b2v;   // rows: g, g+8, 16+g, 24+g
        }

        // ---- softmax over the warp's 32 rows ----
        float m = fmaxf(fmaxf(lg[0], lg[1]), fmaxf(lg[2], lg[3]));
        #pragma unroll
        for (int o = 4; o <= 16; o <<= 1)
            m = fmaxf(m, __shfl_xor_sync(0xffffffffu, m, o));
        float e0 = __expf(lg[0] - m), e1 = __expf(lg[1] - m);
        float e2 = __expf(lg[2] - m), e3 = __expf(lg[3] - m);
        float s = e0 + e1 + e2 + e3;
        #pragma unroll
        for (int o = 4; o <= 16; o <<= 1)
            s += __shfl_xor_sync(0xffffffffu, s, o);
        const float rs = __frcp_rn(s);
        if (tc == 0) {
            swgt[g]      = e0 * rs;
            swgt[g + 8]  = e1 * rs;
            swgt[g + 16] = e2 * rs;
            swgt[g + 24] = e3 * rs;
        }
        __syncwarp();

        // ---- weighted sum of exact fp32 t over k; dims d = 2*lane, 2*lane+1 ----
        {
            const int slot = lane >> 1;          // (2*lane)>>2
            const int off  = (lane & 1) << 1;    // 0 or 2
            float a0 = 0.f, a1 = 0.f;
            #pragma unroll
            for (int r4 = 0; r4 < 8; ++r4) {
                const float4 w4 = swgt4[r4];
                #pragma unroll
                for (int j = 0; j < 4; ++j) {
                    const int rr = r4 * 4 + j;
                    const float w = (j == 0) ? w4.x : (j == 1) ? w4.y : (j == 2) ? w4.z : w4.w;
                    const float2 tv = *(const float2*)&stw[rr * 64 + ((slot ^ (rr & 15)) << 2) + off];
                    a0 += w * tv.x;
                    a1 += w * tv.y;
                }
            }
            float* outp = out + (((size_t)(tower * 3 + 1 + layer)) * 1024 + b) * 256 + f * 64;
            *(float2*)(outp + 2 * lane) = make_float2(a0, a1);
        }
        __syncwarp();

        // ---- T buffer dead (wsum stored): refill for next unit ----
        if (has_next) issue_g(un, tidx_n, Tu);
    }
}

extern "C" void kernel_launch(void* const* d_in, const int* in_sizes, int n_in,
                              void* d_out, int out_size)
{
    const float* node_emb = (const float*)d_in[0];
    // d_in[1] = relation_emb: unused by the reference computation
    const float* W1    = (const float*)d_in[2];
    const float* b1    = (const float*)d_in[3];
    const float* W2    = (const float*)d_in[4];
    const float* b2    = (const float*)d_in[5];
    const int*   users = (const int*)d_in[6];
    const int*   items = (const int*)d_in[7];
    const int*   utri  = (const int*)d_in[8];
    const int*   itri  = (const int*)d_in[9];
    float*       out   = (float*)d_out;

    int nsm = 148;
    cudaDeviceGetAttribute(&nsm, cudaDevAttrMultiProcessorCount, 0);

    cudaFuncSetAttribute(kgat_sched_kernel,
                         cudaFuncAttributeMaxDynamicSharedMemorySize, SMEM_BYTES);
    kgat_sched_kernel<<<nsm, THREADS, SMEM_BYTES>>>(
        node_emb, W1, b1, W2, b2, users, items, utri, itri, out);
}